// round 4
// baseline (speedup 1.0000x reference)
#include <cuda_runtime.h>

// WaveletLayer fused: db2 DWT -> scale -> inverse DWT -> ReLU
// x: (4096,4096) f32, kernel: (4096,2049) f32, out: (4096,4096) f32
//
// R4: one block per row, 16 outputs per thread.
//  - x: 4 aligned LDG.128 per thread (exact coverage), halo via warp shuffle,
//    lane 0/31 patch with scalar loads (symmetric reflect at row ends).
//  - K: 9-value window K[m0..m0+8], block-uniform misalignment d=row&3,
//    covered by 3 aligned LDG.128 + uniform select.
//  - out: 4 STG.128 (.cs streaming hint).

#define NCOL 4096
#define LOUT 2049
#define NT   256
#define FULL 0xffffffffu

__global__ __launch_bounds__(NT) void wavelet_fused_kernel(
    const float* __restrict__ x,
    const float* __restrict__ kern,
    float* __restrict__ out)
{
    const int row  = blockIdx.x;
    const int tid  = threadIdx.x;
    const int m0   = tid * 8;        // first pair index
    const int base = tid * 16;       // first output column
    const int lane = tid & 31;

    const float* xr = x + (size_t)row * NCOL;

    // Core: x[base .. base+15], four aligned float4 loads
    const float4* x4 = reinterpret_cast<const float4*>(xr + base);
    float4 qa = x4[0];
    float4 qb = x4[1];
    float4 qc = x4[2];
    float4 qd = x4[3];

    float c0 = qa.x, c1 = qa.y, c2  = qa.z, c3  = qa.w;
    float c4 = qb.x, c5 = qb.y, c6  = qb.z, c7  = qb.w;
    float c8 = qc.x, c9 = qc.y, c10 = qc.z, c11 = qc.w;
    float c12 = qd.x, c13 = qd.y, c14 = qd.z, c15 = qd.w;

    // Halo via shuffle: left = prev lane's c14,c15 ; right = next lane's c0,c1
    float hl0 = __shfl_up_sync(FULL, c14, 1);   // x[base-2]
    float hl1 = __shfl_up_sync(FULL, c15, 1);   // x[base-1]
    float hr0 = __shfl_down_sync(FULL, c0, 1);  // x[base+16]
    float hr1 = __shfl_down_sync(FULL, c1, 1);  // x[base+17]

    if (lane == 0) {
        if (base == 0) { hl0 = xr[1]; hl1 = xr[0]; }               // reflect
        else           { hl0 = xr[base - 2]; hl1 = xr[base - 1]; }
    }
    if (lane == 31) {
        if (base == NCOL - 16) { hr0 = xr[NCOL - 1]; hr1 = xr[NCOL - 2]; } // reflect
        else                   { hr0 = xr[base + 16]; hr1 = xr[base + 17]; }
    }

    // s[k] = x_sym(base - 2 + k), k = 0..19
    float s[20];
    s[0] = hl0; s[1] = hl1;
    s[2]  = c0;  s[3]  = c1;  s[4]  = c2;  s[5]  = c3;
    s[6]  = c4;  s[7]  = c5;  s[8]  = c6;  s[9]  = c7;
    s[10] = c8;  s[11] = c9;  s[12] = c10; s[13] = c11;
    s[14] = c12; s[15] = c13; s[16] = c14; s[17] = c15;
    s[18] = hr0; s[19] = hr1;

    // K window K[m0 .. m0+8]: uniform misalignment d = row & 3
    const int w = LOUT * row + m0;
    const int d = w & 3;
    const float4* kp = reinterpret_cast<const float4*>(kern + (w - d));
    float4 f0 = kp[0];
    float4 f1 = kp[1];
    float4 f2 = kp[2];
    float kv[9];
    {
        float buf[12] = { f0.x, f0.y, f0.z, f0.w,
                          f1.x, f1.y, f1.z, f1.w,
                          f2.x, f2.y, f2.z, f2.w };
        // d is uniform across the block; unrolled branch keeps everything in regs
        if (d == 0) {
            #pragma unroll
            for (int i = 0; i < 9; i++) kv[i] = buf[i];
        } else if (d == 1) {
            #pragma unroll
            for (int i = 0; i < 9; i++) kv[i] = buf[i + 1];
        } else if (d == 2) {
            #pragma unroll
            for (int i = 0; i < 9; i++) kv[i] = buf[i + 2];
        } else {
            #pragma unroll
            for (int i = 0; i < 9; i++) kv[i] = buf[i + 3];
        }
    }

    const float l0 = -0.12940952255126037f;
    const float l1 =  0.22414386804185735f;
    const float l2 =  0.8365163037378079f;
    const float l3 =  0.48296291314453416f;
    const float h0 = -0.48296291314453416f;
    const float h1 =  0.8365163037378079f;
    const float h2 = -0.22414386804185735f;
    const float h3 = -0.12940952255126037f;

    // A[m], D[m] for m = m0..m0+8, window s[2m..2m+3]
    float A[9], D[9];
    #pragma unroll
    for (int m = 0; m < 9; m++) {
        float a = l3 * s[2 * m] + l2 * s[2 * m + 1]
                + l1 * s[2 * m + 2] + l0 * s[2 * m + 3];
        float dd = h3 * s[2 * m] + h2 * s[2 * m + 1]
                 + h1 * s[2 * m + 2] + h0 * s[2 * m + 3];
        A[m] = a * kv[m];
        D[m] = dd * kv[m];
    }

    float r[16];
    #pragma unroll
    for (int j = 0; j < 8; j++) {
        float ye = l1 * A[j] + l3 * A[j + 1] + h1 * D[j] + h3 * D[j + 1];
        float yo = l0 * A[j] + l2 * A[j + 1] + h0 * D[j] + h2 * D[j + 1];
        r[2 * j]     = fmaxf(ye, 0.0f);
        r[2 * j + 1] = fmaxf(yo, 0.0f);
    }

    float4* o4 = reinterpret_cast<float4*>(out + (size_t)row * NCOL + base);
    __stcs(o4 + 0, make_float4(r[0],  r[1],  r[2],  r[3]));
    __stcs(o4 + 1, make_float4(r[4],  r[5],  r[6],  r[7]));
    __stcs(o4 + 2, make_float4(r[8],  r[9],  r[10], r[11]));
    __stcs(o4 + 3, make_float4(r[12], r[13], r[14], r[15]));
}

extern "C" void kernel_launch(void* const* d_in, const int* in_sizes, int n_in,
                              void* d_out, int out_size)
{
    const float* x    = (const float*)d_in[0];
    const float* kern = (const float*)d_in[1];
    float*       out  = (float*)d_out;

    wavelet_fused_kernel<<<4096, NT>>>(x, kern, out);
}

// round 5
// speedup vs baseline: 1.2749x; 1.2749x over previous
#include <cuda_runtime.h>

// WaveletLayer fused: db2 DWT -> scale -> inverse DWT -> ReLU, fully collapsed.
//
// Using the db2 QMF relation hi[i] = (-1)^i lo[3-i], the composite
// DWT -> per-coefficient scale -> IDWT map reduces exactly to (t = sqrt(3)/4):
//   u = x[2m], v = x[2m+1]
//   p = 0.75u - t*v,  q = u - p
//   r = 0.25v - t*u,  s = v - r
//   out[2m]   = relu(k[m]*p + k[m+1]*q)
//   out[2m+1] = relu(k[m]*r + k[m+1]*s)
// Symmetric-padding contributions cancel identically -> no halo, no boundaries.
//
// x: (4096,4096) f32, kernel: (4096,2049) f32, out: (4096,4096) f32

#define NCOL 4096
#define LOUT 2049
#define NT   256

__global__ __launch_bounds__(NT) void wavelet_fused_kernel(
    const float* __restrict__ x,
    const float* __restrict__ kern,
    float* __restrict__ out)
{
    const int row  = blockIdx.y;
    const int m0   = (blockIdx.x * NT + threadIdx.x) * 4;  // first pair index
    const int base = 2 * m0;                               // first output column

    // x[base .. base+7]: two aligned float4 loads, (u,v) pairs interleaved
    const float4* x4 = reinterpret_cast<const float4*>(x + (size_t)row * NCOL + base);
    float4 X0 = x4[0];
    float4 X1 = x4[1];

    // K window K[m0..m0+4]: block-uniform misalignment d = row & 3,
    // covered by 2 aligned float4 loads + uniform select.
    // (Tail-safe: for the last row d=3, so the read ends exactly at the
    //  last element of kern.)
    const int w = LOUT * row + m0;
    const int d = w & 3;
    const float4* kp = reinterpret_cast<const float4*>(kern + (w - d));
    float4 f0 = kp[0];
    float4 f1 = kp[1];
    float k0, k1, k2, k3, k4;
    if (d == 0)      { k0 = f0.x; k1 = f0.y; k2 = f0.z; k3 = f0.w; k4 = f1.x; }
    else if (d == 1) { k0 = f0.y; k1 = f0.z; k2 = f0.w; k3 = f1.x; k4 = f1.y; }
    else if (d == 2) { k0 = f0.z; k1 = f0.w; k2 = f1.x; k3 = f1.y; k4 = f1.z; }
    else             { k0 = f0.w; k1 = f1.x; k2 = f1.y; k3 = f1.z; k4 = f1.w; }

    const float T = 0.43301270189221932f;  // sqrt(3)/4
    const float A = 0.75f;
    const float B = 0.25f;

    float4 r0, r1;
    {
        float u = X0.x, v = X0.y;
        float p = fmaf(-T, v, A * u); float q = u - p;
        float rr = fmaf(-T, u, B * v); float ss = v - rr;
        r0.x = fmaxf(fmaf(k1, q,  k0 * p),  0.0f);
        r0.y = fmaxf(fmaf(k1, ss, k0 * rr), 0.0f);
    }
    {
        float u = X0.z, v = X0.w;
        float p = fmaf(-T, v, A * u); float q = u - p;
        float rr = fmaf(-T, u, B * v); float ss = v - rr;
        r0.z = fmaxf(fmaf(k2, q,  k1 * p),  0.0f);
        r0.w = fmaxf(fmaf(k2, ss, k1 * rr), 0.0f);
    }
    {
        float u = X1.x, v = X1.y;
        float p = fmaf(-T, v, A * u); float q = u - p;
        float rr = fmaf(-T, u, B * v); float ss = v - rr;
        r1.x = fmaxf(fmaf(k3, q,  k2 * p),  0.0f);
        r1.y = fmaxf(fmaf(k3, ss, k2 * rr), 0.0f);
    }
    {
        float u = X1.z, v = X1.w;
        float p = fmaf(-T, v, A * u); float q = u - p;
        float rr = fmaf(-T, u, B * v); float ss = v - rr;
        r1.z = fmaxf(fmaf(k4, q,  k3 * p),  0.0f);
        r1.w = fmaxf(fmaf(k4, ss, k3 * rr), 0.0f);
    }

    float4* o4 = reinterpret_cast<float4*>(out + (size_t)row * NCOL + base);
    __stcs(o4,     r0);
    __stcs(o4 + 1, r1);
}

extern "C" void kernel_launch(void* const* d_in, const int* in_sizes, int n_in,
                              void* d_out, int out_size)
{
    const float* x    = (const float*)d_in[0];
    const float* kern = (const float*)d_in[1];
    float*       out  = (float*)d_out;

    dim3 grid(2, 4096);   // 2 blocks x 256 threads x 4 pairs = 2048 pairs/row
    wavelet_fused_kernel<<<grid, NT>>>(x, kern, out);
}